// round 15
// baseline (speedup 1.0000x reference)
#include <cuda_runtime.h>
#include <cstdint>

#define NDIM 8192
#define THREADS 256
#define NBLOCKS 592                    // 148 SMs * 4 CTAs/SM -> one wave
#define NITEMS (NDIM * 8)              // 65536 eighth-row items (256 vecs each)

// Scratch for deterministic two-stage reduction (no cudaMalloc allowed).
__device__ float g_partA[NBLOCKS];
__device__ float g_partB[NBLOCKS];
__device__ int   g_count = 0;

// Packed f32x2 helpers (sm_103a).
__device__ __forceinline__ void fma2(unsigned long long& d,
                                     unsigned long long a,
                                     unsigned long long b) {
    asm("fma.rn.f32x2 %0, %1, %2, %0;" : "+l"(d) : "l"(a), "l"(b));
}
__device__ __forceinline__ void add2(unsigned long long& d,
                                     unsigned long long a) {
    asm("add.rn.f32x2 %0, %0, %1;" : "+l"(d) : "l"(a));
}
__device__ __forceinline__ float lo2(unsigned long long p) {
    unsigned int l, h;
    asm("mov.b64 {%0, %1}, %2;" : "=r"(l), "=r"(h) : "l"(p));
    return __uint_as_float(l);
}
__device__ __forceinline__ float hi2(unsigned long long p) {
    unsigned int l, h;
    asm("mov.b64 {%0, %1}, %2;" : "=r"(l), "=r"(h) : "l"(p));
    return __uint_as_float(h);
}

__global__ __launch_bounds__(THREADS, 4)
void ising_fused(const float* __restrict__ M, const float* __restrict__ s,
                 float* __restrict__ out) {
    __shared__ float s_sh[NDIM];          // 32 KB staged state vector
    __shared__ float sA[THREADS / 32];
    __shared__ float sB[THREADS / 32];
    __shared__ int s_isLast;

    const int tid  = threadIdx.x;
    const int lane = tid & 31;
    const int wid  = tid >> 5;
    const int bid  = blockIdx.x;

    // Stage state vector into shared (vectorized, coalesced).
    {
        const float4* s4g = reinterpret_cast<const float4*>(s);
        float4* sh4w = reinterpret_cast<float4*>(s_sh);
        #pragma unroll
        for (int k = tid; k < NDIM / 4; k += THREADS) sh4w[k] = s4g[k];
    }
    __syncthreads();

    const ulonglong2* s64 = reinterpret_cast<const ulonglong2*>(s_sh);
    const ulonglong2* M64 = reinterpret_cast<const ulonglong2*>(M);

    // Exactly-equal partition at eighth-row granularity (110 or 111 items).
    const int itemBeg = (int)(((long long)bid * NITEMS) / NBLOCKS);
    const int itemEnd = (int)(((long long)(bid + 1) * NITEMS) / NBLOCKS);

    unsigned long long a01 = 0ull, a23 = 0ull;   // packed plain sum
    unsigned long long d01 = 0ull, d23 = 0ull;   // packed dot for current row
    float amAcc = 0.0f;                          // mixed-vec plain remainder
    float dm    = 0.0f;                          // mixed-vec dot remainder
    float bAcc  = 0.0f;                          // s_i-weighted upper-dot + diag

    int curRow = itemBeg >> 3;

    #pragma unroll 1
    for (int g = itemBeg; g < itemEnd; g += 8) {
        // Batch-issue 8 independent coalesced LDG.128 (MLP=8); addresses for
        // items past itemEnd are clamped (loaded but never consumed).
        ulonglong2 v[8];
        #pragma unroll
        for (int i = 0; i < 8; ++i) {
            int gi = g + i;
            gi = (gi < itemEnd) ? gi : (itemEnd - 1);
            const size_t addr = (size_t)(gi >> 3) * 2048 + ((gi & 7) << 8) + tid;
            v[i] = __ldcs(M64 + addr);
        }

        #pragma unroll
        for (int i = 0; i < 8; ++i) {
            const int gi = g + i;
            if (gi >= itemEnd) break;             // warp-uniform guard
            const int row = gi >> 3;
            const int j4  = ((gi & 7) << 8) + tid;
            const int vs  = row >> 2;

            if (row != curRow) {                  // fold finished row (uniform)
                const float di =
                    ((lo2(d01) + hi2(d01)) + (lo2(d23) + hi2(d23))) + dm;
                bAcc = fmaf(s_sh[curRow], di, bAcc);
                d01 = 0ull; d23 = 0ull; dm = 0.0f;
                curRow = row;
            }

            const ulonglong2 vv = v[i];
            if (j4 > vs) {
                // strictly above diagonal: sum + dot
                const ulonglong2 tt = s64[j4];    // LDS.128, conflict-free
                add2(a01, vv.x);  add2(a23, vv.y);
                fma2(d01, vv.x, tt.x);  fma2(d23, vv.y, tt.y);
            } else if (j4 < vs) {
                // strictly below diagonal: sum only
                add2(a01, vv.x);  add2(a23, vv.y);
            } else {
                // the one vec containing the diagonal: element-wise selects
                const float vx = lo2(vv.x), vy = hi2(vv.x);
                const float vz = lo2(vv.y), vw = hi2(vv.y);
                const ulonglong2 tt = s64[j4];
                const float tx = lo2(tt.x), ty = hi2(tt.x);
                const float tz = lo2(tt.y), tw = hi2(tt.y);
                const int j = j4 * 4;
                amAcc += (vx + vy) + (vz + vw);
                const float w0 = (j + 0 > row) ? tx : ((j + 0 == row) ? 1.0f : 0.0f);
                const float w1 = (j + 1 > row) ? ty : ((j + 1 == row) ? 1.0f : 0.0f);
                const float w2 = (j + 2 > row) ? tz : ((j + 2 == row) ? 1.0f : 0.0f);
                const float w3 = (j + 3 > row) ? tw : ((j + 3 == row) ? 1.0f : 0.0f);
                dm += fmaf(vx, w0, fmaf(vy, w1, fmaf(vz, w2, vw * w3)));
            }
        }
    }

    // Fold the last open row.
    {
        const float di = ((lo2(d01) + hi2(d01)) + (lo2(d23) + hi2(d23))) + dm;
        bAcc = fmaf(s_sh[curRow], di, bAcc);
    }

    float aAcc = ((lo2(a01) + hi2(a01)) + (lo2(a23) + hi2(a23))) + amAcc;

    // Warp shuffle reduction (deterministic).
    #pragma unroll
    for (int off = 16; off > 0; off >>= 1) {
        aAcc += __shfl_xor_sync(0xFFFFFFFFu, aAcc, off);
        bAcc += __shfl_xor_sync(0xFFFFFFFFu, bAcc, off);
    }
    if (lane == 0) { sA[wid] = aAcc; sB[wid] = bAcc; }
    __syncthreads();

    if (tid == 0) {
        float a = 0.f, b = 0.f;
        #pragma unroll
        for (int w = 0; w < THREADS / 32; ++w) { a += sA[w]; b += sB[w]; }
        g_partA[bid] = a;
        g_partB[bid] = b;
        __threadfence();
        const int prev = atomicAdd(&g_count, 1);
        s_isLast = (prev == NBLOCKS - 1);
    }
    __syncthreads();

    // Last block: deterministic final reduction in double (reuses s_sh space).
    if (s_isLast) {
        double* rA = reinterpret_cast<double*>(s_sh);
        double* rB = rA + THREADS;
        double a = 0.0, b = 0.0;
        #pragma unroll 2
        for (int k = tid; k < NBLOCKS; k += THREADS) {
            a += (double)g_partA[k];
            b += (double)g_partB[k];
        }
        rA[tid] = a;
        rB[tid] = b;
        __syncthreads();
        #pragma unroll
        for (int st = THREADS / 2; st > 0; st >>= 1) {
            if (tid < st) { rA[tid] += rA[tid + st]; rB[tid] += rB[tid + st]; }
            __syncthreads();
        }
        if (tid == 0) {
            // out = sum(M)/4 - 0.5 * (sum_{i<j} M_ij s_i s_j + sum_i M_ii s_i)
            out[0] = (float)(rA[0] * 0.25 - 0.5 * rB[0]);
            g_count = 0;   // reset for next graph replay
        }
    }
}

extern "C" void kernel_launch(void* const* d_in, const int* in_sizes, int n_in,
                              void* d_out, int out_size) {
    const float* M = (const float*)d_in[0];   // info_mtx [8192, 8192] fp32
    const float* s = (const float*)d_in[1];   // state [8192] fp32
    float* out = (float*)d_out;

    ising_fused<<<NBLOCKS, THREADS>>>(M, s, out);
}

// round 16
// speedup vs baseline: 1.0463x; 1.0463x over previous
#include <cuda_runtime.h>
#include <cstdint>

#define NDIM 8192
#define THREADS 256
#define NBLOCKS 592                    // 148 SMs * 4 CTAs/SM -> one wave

// Scratch for deterministic two-stage reduction (no cudaMalloc allowed).
__device__ float g_partA[NBLOCKS];
__device__ float g_partB[NBLOCKS];
__device__ int   g_count = 0;

// Packed f32x2 helpers (sm_103a).
__device__ __forceinline__ void fma2(unsigned long long& d,
                                     unsigned long long a,
                                     unsigned long long b) {
    asm("fma.rn.f32x2 %0, %1, %2, %0;" : "+l"(d) : "l"(a), "l"(b));
}
__device__ __forceinline__ void add2(unsigned long long& d,
                                     unsigned long long a) {
    asm("add.rn.f32x2 %0, %0, %1;" : "+l"(d) : "l"(a));
}
__device__ __forceinline__ float lo2(unsigned long long p) {
    unsigned int l, h;
    asm("mov.b64 {%0, %1}, %2;" : "=r"(l), "=r"(h) : "l"(p));
    return __uint_as_float(l);
}
__device__ __forceinline__ float hi2(unsigned long long p) {
    unsigned int l, h;
    asm("mov.b64 {%0, %1}, %2;" : "=r"(l), "=r"(h) : "l"(p));
    return __uint_as_float(h);
}

// Balanced partition: every CTA gets 14 rows except bids 444..539 (13 rows).
// Residue classes mod 148 (= co-resident on one SM) then sum to 55 or 56 rows
// instead of the floor-partition's degenerate 52-vs-56.
__device__ __forceinline__ int rowBegOf(int bid) {
    int c = bid - 444;
    c = (c < 0) ? 0 : ((c > 96) ? 96 : c);
    return 14 * bid - c;
}

__global__ __launch_bounds__(THREADS, 4)
void ising_fused(const float* __restrict__ M, const float* __restrict__ s,
                 float* __restrict__ out) {
    __shared__ float s_sh[NDIM];          // 32 KB staged state vector
    __shared__ float sA[THREADS / 32];
    __shared__ float sB[THREADS / 32];
    __shared__ int s_isLast;

    const int tid  = threadIdx.x;
    const int lane = tid & 31;
    const int wid  = tid >> 5;
    const int bid  = blockIdx.x;

    // Stage state vector into shared (vectorized, coalesced).
    {
        const float4* s4g = reinterpret_cast<const float4*>(s);
        float4* sh4w = reinterpret_cast<float4*>(s_sh);
        #pragma unroll
        for (int k = tid; k < NDIM / 4; k += THREADS) sh4w[k] = s4g[k];
    }
    __syncthreads();

    const ulonglong2* s64 = reinterpret_cast<const ulonglong2*>(s_sh);

    // SM-balanced contiguous row partition (see rowBegOf).
    const int rowBeg = rowBegOf(bid);
    const int rowEnd = rowBegOf(bid + 1);

    unsigned long long a01 = 0ull, a23 = 0ull;   // packed plain sum
    float amAcc = 0.0f;                          // mixed-vec plain-sum remainder
    float bAcc  = 0.0f;                          // s_i-weighted upper-dot + diag

    #pragma unroll 1
    for (int row = rowBeg; row < rowEnd; ++row) {
        const ulonglong2* row64 =
            reinterpret_cast<const ulonglong2*>(M + (size_t)row * NDIM);

        // Batch-issue the whole row: 8 independent coalesced LDG.128 (MLP=8),
        // streaming policy (evict-first; M is touched exactly once).
        ulonglong2 v[8];
        #pragma unroll
        for (int k = 0; k < 8; ++k) v[k] = __ldcs(row64 + tid + k * 256);

        const int vs = row >> 2;          // vec index containing the diagonal
        unsigned long long d01 = 0ull, d23 = 0ull;
        float dm = 0.0f;

        #pragma unroll
        for (int k = 0; k < 8; ++k) {
            const int j4 = tid + k * 256;
            const ulonglong2 vv = v[k];
            if (j4 > vs) {
                // strictly above diagonal: sum + dot (warp-uniform in all but one warp)
                const ulonglong2 tt = s64[j4];       // LDS.128, conflict-free
                add2(a01, vv.x);  add2(a23, vv.y);
                fma2(d01, vv.x, tt.x);  fma2(d23, vv.y, tt.y);
            } else if (j4 < vs) {
                // strictly below diagonal: sum only
                add2(a01, vv.x);  add2(a23, vv.y);
            } else {
                // the one vec containing the diagonal: element-wise selects
                const float vx = lo2(vv.x), vy = hi2(vv.x);
                const float vz = lo2(vv.y), vw = hi2(vv.y);
                const ulonglong2 tt = s64[j4];
                const float tx = lo2(tt.x), ty = hi2(tt.x);
                const float tz = lo2(tt.y), tw = hi2(tt.y);
                const int j = j4 * 4;
                amAcc += (vx + vy) + (vz + vw);
                const float w0 = (j + 0 > row) ? tx : ((j + 0 == row) ? 1.0f : 0.0f);
                const float w1 = (j + 1 > row) ? ty : ((j + 1 == row) ? 1.0f : 0.0f);
                const float w2 = (j + 2 > row) ? tz : ((j + 2 == row) ? 1.0f : 0.0f);
                const float w3 = (j + 3 > row) ? tw : ((j + 3 == row) ? 1.0f : 0.0f);
                dm += fmaf(vx, w0, fmaf(vy, w1, fmaf(vz, w2, vw * w3)));
            }
        }

        // Fold this row's dot, weighted by s_row.
        const float di = ((lo2(d01) + hi2(d01)) + (lo2(d23) + hi2(d23))) + dm;
        bAcc = fmaf(s_sh[row], di, bAcc);
    }

    float aAcc = ((lo2(a01) + hi2(a01)) + (lo2(a23) + hi2(a23))) + amAcc;

    // Warp shuffle reduction (deterministic).
    #pragma unroll
    for (int off = 16; off > 0; off >>= 1) {
        aAcc += __shfl_xor_sync(0xFFFFFFFFu, aAcc, off);
        bAcc += __shfl_xor_sync(0xFFFFFFFFu, bAcc, off);
    }
    if (lane == 0) { sA[wid] = aAcc; sB[wid] = bAcc; }
    __syncthreads();

    if (tid == 0) {
        float a = 0.f, b = 0.f;
        #pragma unroll
        for (int w = 0; w < THREADS / 32; ++w) { a += sA[w]; b += sB[w]; }
        g_partA[bid] = a;
        g_partB[bid] = b;
        __threadfence();
        const int prev = atomicAdd(&g_count, 1);
        s_isLast = (prev == NBLOCKS - 1);
    }
    __syncthreads();

    // Last block: deterministic final reduction in double (reuses s_sh space).
    if (s_isLast) {
        double* rA = reinterpret_cast<double*>(s_sh);
        double* rB = rA + THREADS;
        double a = 0.0, b = 0.0;
        #pragma unroll 2
        for (int k = tid; k < NBLOCKS; k += THREADS) {
            a += (double)g_partA[k];
            b += (double)g_partB[k];
        }
        rA[tid] = a;
        rB[tid] = b;
        __syncthreads();
        #pragma unroll
        for (int st = THREADS / 2; st > 0; st >>= 1) {
            if (tid < st) { rA[tid] += rA[tid + st]; rB[tid] += rB[tid + st]; }
            __syncthreads();
        }
        if (tid == 0) {
            // out = sum(M)/4 - 0.5 * (sum_{i<j} M_ij s_i s_j + sum_i M_ii s_i)
            out[0] = (float)(rA[0] * 0.25 - 0.5 * rB[0]);
            g_count = 0;   // reset for next graph replay
        }
    }
}

extern "C" void kernel_launch(void* const* d_in, const int* in_sizes, int n_in,
                              void* d_out, int out_size) {
    const float* M = (const float*)d_in[0];   // info_mtx [8192, 8192] fp32
    const float* s = (const float*)d_in[1];   // state [8192] fp32
    float* out = (float*)d_out;

    ising_fused<<<NBLOCKS, THREADS>>>(M, s, out);
}